// round 15
// baseline (speedup 1.0000x reference)
#include <cuda_runtime.h>
#include <cuda_bf16.h>

// Shapes fixed by the reference setup_inputs:
//   L = 512, Lp = 64, K = 17, features_dim = 56
// Output layout (float32, out_size elements):
//   [0 .. L*51*56*56)    features_poses (broadcast of pred_poses flat (L,51))
//   [out_size-1]         loss scalar
//
// Fill = mandated 327.5 MB store stream at the B300 store ceiling
// (~6.5 TB/s sustained across 8 measured structures). This round probes the
// last untested store policy: __stwt (write-through, no L2 dirty state /
// writeback double-transit) in place of __stcs.
#define L_DIM      512
#define LP_DIM     64
#define K_DIM      17
#define VEC_PER_CH 784u                  // 3136 floats / 4 per channel

#define NB_LOSS    128                   // 4 l-rows per block, 512 total
#define NB_FILL    4998                  // 4998*256*16 == 20,471,808 == nvec
#define THREADS    256

__device__ float    g_partial[L_DIM];
__device__ unsigned g_ticket = 0;

// ---------------------------------------------------------------------------
// Fused kernel.
//   blockIdx.x <  NB_LOSS : loss partials (4 l-rows each); last block reduces
//   blockIdx.x >= NB_LOSS : broadcast fill, grid-stride float4 write-through
//                           stores (self-balancing, exact 16 iters/thread)
// ---------------------------------------------------------------------------
__global__ void __launch_bounds__(THREADS)
fused_kernel(const float* __restrict__ pred_poses,    // (512,17,3)
             const float* __restrict__ target_poses,  // (64,17,3)
             const float* __restrict__ pred_fb,       // (512,)
             const float* __restrict__ ious,          // (512,64)
             const float* __restrict__ areas,         // (64,)
             float*       __restrict__ out,           // (out_size,)
             unsigned nvec,                           // float4 count
             float*       __restrict__ loss_out)      // &out[out_size-1]
{
    const int tid = threadIdx.x;

    if (blockIdx.x >= NB_LOSS) {
        // ----------------- broadcast fill (store-bound) -----------------
        float4* __restrict__ ov = (float4*)out;
        unsigned i      = (blockIdx.x - NB_LOSS) * THREADS + tid;
        const unsigned stride = NB_FILL * THREADS;
#pragma unroll 4
        for (; i < nvec; i += stride) {
            float v = __ldg(&pred_poses[i / VEC_PER_CH]);
            __stwt(&ov[i], make_float4(v, v, v, v));   // write-through
        }
        return;
    }

    // ----------------- loss partials: 4 l-rows per block -----------------
    const int l_sub = tid >> 6;           // 0..3
    const int lp    = tid & 63;           // 0..63
    const int l     = blockIdx.x * 4 + l_sub;

    __shared__ float s_px[4][K_DIM], s_py[4][K_DIM];
    __shared__ float s_logp[4][K_DIM], s_log1mp[4][K_DIM];

    if (lp < K_DIM) {
        const float* pp = pred_poses + (l * K_DIM + lp) * 3;
        float x = pp[0], y = pp[1], v = pp[2];
        v = fminf(fmaxf(v, 1e-7f), 1.0f - 1e-7f);
        s_px[l_sub][lp]     = x;
        s_py[l_sub][lp]     = y;
        s_logp[l_sub][lp]   = logf(v);
        s_log1mp[l_sub][lp] = logf(1.0f - v);
    }
    __syncthreads();

    const float inv2a = 1.0f / (2.0f * areas[lp] + 1e-6f);

    float fb_sum  = 0.0f;
    float bce_sum = 0.0f;
#pragma unroll
    for (int k = 0; k < K_DIM; k++) {
        const float* tp = target_poses + (lp * K_DIM + k) * 3;
        float tx = tp[0], ty = tp[1], tv = tp[2];
        float dx = s_px[l_sub][k] - tx;
        float dy = s_py[l_sub][k] - ty;
        float d2 = dx * dx + dy * dy;
        fb_sum  += expf(-d2 * inv2a);
        bce_sum -= tv * s_logp[l_sub][k] + (1.0f - tv) * s_log1mp[l_sub][k];
    }

    const float inv_k = 1.0f / (float)K_DIM;
    float fl  = pred_fb[l] - fb_sum * inv_k;
    fl *= fl;
    float s = ious[l * LP_DIM + lp] * (fl + bce_sum * inv_k);

    // 64 lanes per l-row = 2 warps: shuffle then pairwise combine
#pragma unroll
    for (int off = 16; off > 0; off >>= 1)
        s += __shfl_down_sync(0xffffffffu, s, off);

    __shared__ float wsum[8];
    if ((tid & 31) == 0) wsum[tid >> 5] = s;
    __syncthreads();
    if (lp == 0) g_partial[l] = wsum[2 * l_sub] + wsum[2 * l_sub + 1];

    // ----------------- last loss block reduces 512 -> 1 -----------------
    __shared__ unsigned s_last;
    if (tid == 0) {
        __threadfence();
        s_last = (atomicAdd(&g_ticket, 1u) == NB_LOSS - 1) ? 1u : 0u;
    }
    __syncthreads();
    if (!s_last) return;

    __shared__ float sh[THREADS];
    sh[tid] = g_partial[tid] + g_partial[tid + THREADS];
    __syncthreads();
#pragma unroll
    for (int off = THREADS / 2; off > 0; off >>= 1) {
        if (tid < off) sh[tid] += sh[tid + off];
        __syncthreads();
    }
    if (tid == 0) {
        loss_out[0] = sh[0];
        g_ticket = 0;                     // reset for graph replay
    }
}

// ---------------------------------------------------------------------------
extern "C" void kernel_launch(void* const* d_in, const int* in_sizes, int n_in,
                              void* d_out, int out_size)
{
    const float* pred_poses   = (const float*)d_in[0];
    const float* target_poses = (const float*)d_in[1];
    const float* pred_fb      = (const float*)d_in[2];
    const float* ious         = (const float*)d_in[3];
    const float* areas        = (const float*)d_in[4];

    float* out = (float*)d_out;
    unsigned nvec = (unsigned)((out_size - 1) / 4);   // 20,471,808

    fused_kernel<<<NB_LOSS + NB_FILL, THREADS>>>(
        pred_poses, target_poses, pred_fb, ious, areas,
        out, nvec, out + (out_size - 1));
}

// round 16
// speedup vs baseline: 1.1296x; 1.1296x over previous
#include <cuda_runtime.h>
#include <cuda_bf16.h>

// Shapes fixed by the reference setup_inputs:
//   L = 512, Lp = 64, K = 17, features_dim = 56
// Output layout (float32, out_size elements):
//   [0 .. L*51*56*56)    features_poses (broadcast of pred_poses flat (L,51))
//   [out_size-1]         loss scalar
//
// FINAL. The fill is a mandated 327.5 MB store stream running at the B300
// store roofline (~6.6 TB/s sustained). Exhaustive search: fill structure
// (grid-stride / warp-owns-channel / single-wave persistent), store policy
// (default / .cs / .wt / TMA bulk), block size, unroll depth, and launch
// fusion. Winner: fused single launch, grid-stride float4 __stcs stores
// (L2 retained as write coalescer), loss fully hidden under the fill.
#define L_DIM      512
#define LP_DIM     64
#define K_DIM      17
#define VEC_PER_CH 784u                  // 3136 floats / 4 per channel

#define NB_LOSS    128                   // 4 l-rows per block, 512 total
#define NB_FILL    4998                  // 4998*256*16 == 20,471,808 == nvec
#define THREADS    256

__device__ float    g_partial[L_DIM];
__device__ unsigned g_ticket = 0;

// ---------------------------------------------------------------------------
// Fused kernel (best-known configuration; at the store roofline).
//   blockIdx.x <  NB_LOSS : loss partials (4 l-rows each); last block reduces
//   blockIdx.x >= NB_LOSS : broadcast fill, grid-stride float4 streaming
//                           stores (self-balancing, exact 16 iters/thread)
// ---------------------------------------------------------------------------
__global__ void __launch_bounds__(THREADS)
fused_kernel(const float* __restrict__ pred_poses,    // (512,17,3)
             const float* __restrict__ target_poses,  // (64,17,3)
             const float* __restrict__ pred_fb,       // (512,)
             const float* __restrict__ ious,          // (512,64)
             const float* __restrict__ areas,         // (64,)
             float*       __restrict__ out,           // (out_size,)
             unsigned nvec,                           // float4 count
             float*       __restrict__ loss_out)      // &out[out_size-1]
{
    const int tid = threadIdx.x;

    if (blockIdx.x >= NB_LOSS) {
        // ----------------- broadcast fill (store-bound) -----------------
        float4* __restrict__ ov = (float4*)out;
        unsigned i      = (blockIdx.x - NB_LOSS) * THREADS + tid;
        const unsigned stride = NB_FILL * THREADS;
#pragma unroll 4
        for (; i < nvec; i += stride) {
            float v = __ldg(&pred_poses[i / VEC_PER_CH]);
            __stcs(&ov[i], make_float4(v, v, v, v));
        }
        return;
    }

    // ----------------- loss partials: 4 l-rows per block -----------------
    const int l_sub = tid >> 6;           // 0..3
    const int lp    = tid & 63;           // 0..63
    const int l     = blockIdx.x * 4 + l_sub;

    __shared__ float s_px[4][K_DIM], s_py[4][K_DIM];
    __shared__ float s_logp[4][K_DIM], s_log1mp[4][K_DIM];

    if (lp < K_DIM) {
        const float* pp = pred_poses + (l * K_DIM + lp) * 3;
        float x = pp[0], y = pp[1], v = pp[2];
        v = fminf(fmaxf(v, 1e-7f), 1.0f - 1e-7f);
        s_px[l_sub][lp]     = x;
        s_py[l_sub][lp]     = y;
        s_logp[l_sub][lp]   = logf(v);
        s_log1mp[l_sub][lp] = logf(1.0f - v);
    }
    __syncthreads();

    const float inv2a = 1.0f / (2.0f * areas[lp] + 1e-6f);

    float fb_sum  = 0.0f;
    float bce_sum = 0.0f;
#pragma unroll
    for (int k = 0; k < K_DIM; k++) {
        const float* tp = target_poses + (lp * K_DIM + k) * 3;
        float tx = tp[0], ty = tp[1], tv = tp[2];
        float dx = s_px[l_sub][k] - tx;
        float dy = s_py[l_sub][k] - ty;
        float d2 = dx * dx + dy * dy;
        fb_sum  += expf(-d2 * inv2a);
        bce_sum -= tv * s_logp[l_sub][k] + (1.0f - tv) * s_log1mp[l_sub][k];
    }

    const float inv_k = 1.0f / (float)K_DIM;
    float fl  = pred_fb[l] - fb_sum * inv_k;
    fl *= fl;
    float s = ious[l * LP_DIM + lp] * (fl + bce_sum * inv_k);

    // 64 lanes per l-row = 2 warps: shuffle then pairwise combine
#pragma unroll
    for (int off = 16; off > 0; off >>= 1)
        s += __shfl_down_sync(0xffffffffu, s, off);

    __shared__ float wsum[8];
    if ((tid & 31) == 0) wsum[tid >> 5] = s;
    __syncthreads();
    if (lp == 0) g_partial[l] = wsum[2 * l_sub] + wsum[2 * l_sub + 1];

    // ----------------- last loss block reduces 512 -> 1 -----------------
    __shared__ unsigned s_last;
    if (tid == 0) {
        __threadfence();
        s_last = (atomicAdd(&g_ticket, 1u) == NB_LOSS - 1) ? 1u : 0u;
    }
    __syncthreads();
    if (!s_last) return;

    __shared__ float sh[THREADS];
    sh[tid] = g_partial[tid] + g_partial[tid + THREADS];
    __syncthreads();
#pragma unroll
    for (int off = THREADS / 2; off > 0; off >>= 1) {
        if (tid < off) sh[tid] += sh[tid + off];
        __syncthreads();
    }
    if (tid == 0) {
        loss_out[0] = sh[0];
        g_ticket = 0;                     // reset for graph replay
    }
}

// ---------------------------------------------------------------------------
extern "C" void kernel_launch(void* const* d_in, const int* in_sizes, int n_in,
                              void* d_out, int out_size)
{
    const float* pred_poses   = (const float*)d_in[0];
    const float* target_poses = (const float*)d_in[1];
    const float* pred_fb      = (const float*)d_in[2];
    const float* ious         = (const float*)d_in[3];
    const float* areas        = (const float*)d_in[4];

    float* out = (float*)d_out;
    unsigned nvec = (unsigned)((out_size - 1) / 4);   // 20,471,808

    fused_kernel<<<NB_LOSS + NB_FILL, THREADS>>>(
        pred_poses, target_poses, pred_fb, ious, areas,
        out, nvec, out + (out_size - 1));
}

// round 17
// speedup vs baseline: 1.1601x; 1.0270x over previous
#include <cuda_runtime.h>
#include <cuda_bf16.h>

// Shapes fixed by the reference setup_inputs:
//   L = 512, Lp = 64, K = 17, features_dim = 56
// Output layout (float32, out_size elements):
//   [0 .. L*51*56*56)    features_poses (broadcast of pred_poses flat (L,51))
//   [out_size-1]         loss scalar
//
// FINAL. The fill is a mandated 327.5 MB store stream running at the B300
// store roofline (~6.5-6.7 TB/s sustained). Exhaustive search over fill
// structure (grid-stride / warp-owns-channel / single-wave persistent),
// store policy (default / .cs / .wt / TMA bulk), block size, unroll depth,
// and launch fusion. Winner: fused single launch, grid-stride float4 __stcs
// stores (L2 retained as write coalescer), loss fully hidden under the fill.
#define L_DIM      512
#define LP_DIM     64
#define K_DIM      17
#define VEC_PER_CH 784u                  // 3136 floats / 4 per channel

#define NB_LOSS    128                   // 4 l-rows per block, 512 total
#define NB_FILL    4998                  // 4998*256*16 == 20,471,808 == nvec
#define THREADS    256

__device__ float    g_partial[L_DIM];
__device__ unsigned g_ticket = 0;

// ---------------------------------------------------------------------------
// Fused kernel (best-known configuration; at the store roofline).
//   blockIdx.x <  NB_LOSS : loss partials (4 l-rows each); last block reduces
//   blockIdx.x >= NB_LOSS : broadcast fill, grid-stride float4 streaming
//                           stores (self-balancing, exact 16 iters/thread)
// ---------------------------------------------------------------------------
__global__ void __launch_bounds__(THREADS)
fused_kernel(const float* __restrict__ pred_poses,    // (512,17,3)
             const float* __restrict__ target_poses,  // (64,17,3)
             const float* __restrict__ pred_fb,       // (512,)
             const float* __restrict__ ious,          // (512,64)
             const float* __restrict__ areas,         // (64,)
             float*       __restrict__ out,           // (out_size,)
             unsigned nvec,                           // float4 count
             float*       __restrict__ loss_out)      // &out[out_size-1]
{
    const int tid = threadIdx.x;

    if (blockIdx.x >= NB_LOSS) {
        // ----------------- broadcast fill (store-bound) -----------------
        float4* __restrict__ ov = (float4*)out;
        unsigned i      = (blockIdx.x - NB_LOSS) * THREADS + tid;
        const unsigned stride = NB_FILL * THREADS;
#pragma unroll 4
        for (; i < nvec; i += stride) {
            float v = __ldg(&pred_poses[i / VEC_PER_CH]);
            __stcs(&ov[i], make_float4(v, v, v, v));
        }
        return;
    }

    // ----------------- loss partials: 4 l-rows per block -----------------
    const int l_sub = tid >> 6;           // 0..3
    const int lp    = tid & 63;           // 0..63
    const int l     = blockIdx.x * 4 + l_sub;

    __shared__ float s_px[4][K_DIM], s_py[4][K_DIM];
    __shared__ float s_logp[4][K_DIM], s_log1mp[4][K_DIM];

    if (lp < K_DIM) {
        const float* pp = pred_poses + (l * K_DIM + lp) * 3;
        float x = pp[0], y = pp[1], v = pp[2];
        v = fminf(fmaxf(v, 1e-7f), 1.0f - 1e-7f);
        s_px[l_sub][lp]     = x;
        s_py[l_sub][lp]     = y;
        s_logp[l_sub][lp]   = logf(v);
        s_log1mp[l_sub][lp] = logf(1.0f - v);
    }
    __syncthreads();

    const float inv2a = 1.0f / (2.0f * areas[lp] + 1e-6f);

    float fb_sum  = 0.0f;
    float bce_sum = 0.0f;
#pragma unroll
    for (int k = 0; k < K_DIM; k++) {
        const float* tp = target_poses + (lp * K_DIM + k) * 3;
        float tx = tp[0], ty = tp[1], tv = tp[2];
        float dx = s_px[l_sub][k] - tx;
        float dy = s_py[l_sub][k] - ty;
        float d2 = dx * dx + dy * dy;
        fb_sum  += expf(-d2 * inv2a);
        bce_sum -= tv * s_logp[l_sub][k] + (1.0f - tv) * s_log1mp[l_sub][k];
    }

    const float inv_k = 1.0f / (float)K_DIM;
    float fl  = pred_fb[l] - fb_sum * inv_k;
    fl *= fl;
    float s = ious[l * LP_DIM + lp] * (fl + bce_sum * inv_k);

    // 64 lanes per l-row = 2 warps: shuffle then pairwise combine
#pragma unroll
    for (int off = 16; off > 0; off >>= 1)
        s += __shfl_down_sync(0xffffffffu, s, off);

    __shared__ float wsum[8];
    if ((tid & 31) == 0) wsum[tid >> 5] = s;
    __syncthreads();
    if (lp == 0) g_partial[l] = wsum[2 * l_sub] + wsum[2 * l_sub + 1];

    // ----------------- last loss block reduces 512 -> 1 -----------------
    __shared__ unsigned s_last;
    if (tid == 0) {
        __threadfence();
        s_last = (atomicAdd(&g_ticket, 1u) == NB_LOSS - 1) ? 1u : 0u;
    }
    __syncthreads();
    if (!s_last) return;

    __shared__ float sh[THREADS];
    sh[tid] = g_partial[tid] + g_partial[tid + THREADS];
    __syncthreads();
#pragma unroll
    for (int off = THREADS / 2; off > 0; off >>= 1) {
        if (tid < off) sh[tid] += sh[tid + off];
        __syncthreads();
    }
    if (tid == 0) {
        loss_out[0] = sh[0];
        g_ticket = 0;                     // reset for graph replay
    }
}

// ---------------------------------------------------------------------------
extern "C" void kernel_launch(void* const* d_in, const int* in_sizes, int n_in,
                              void* d_out, int out_size)
{
    const float* pred_poses   = (const float*)d_in[0];
    const float* target_poses = (const float*)d_in[1];
    const float* pred_fb      = (const float*)d_in[2];
    const float* ious         = (const float*)d_in[3];
    const float* areas        = (const float*)d_in[4];

    float* out = (float*)d_out;
    unsigned nvec = (unsigned)((out_size - 1) / 4);   // 20,471,808

    fused_kernel<<<NB_LOSS + NB_FILL, THREADS>>>(
        pred_poses, target_poses, pred_fb, ious, areas,
        out, nvec, out + (out_size - 1));
}